// round 1
// baseline (speedup 1.0000x reference)
#include <cuda_runtime.h>

#define NPTS 16000
#define BSZ  8
#define GPT  2000
#define CIN  128
#define COUT 128
#define DX   400
#define DY   400
#define DZ   31          // fp32: (0.9f-(-2.3f))/0.1f = 31.999998... -> 31
#define KOFF 125
#define KC   62          // center offset index

#define HBITS 16
#define HSIZE (1 << HBITS)
#define HMASK (HSIZE - 1)
#define MAXP  (1 << 20)

// ---- scratch (device globals; no allocations allowed) ----
__device__ unsigned int g_keys[HSIZE];
__device__ int          g_vals[HSIZE];
__device__ int          g_pidx[NPTS];     // packed voxel idx per point
__device__ int          g_jc[NPTS];       // center-cell gather index (or -1)
__device__ int          g_pairs[3 * MAXP];
__device__ int          g_paircnt;

__device__ __forceinline__ unsigned int hash_key(unsigned int key) {
    return (key * 2654435761u) >> (32 - HBITS);
}

// ---------------------------------------------------------------------------
__global__ void k_clear() {
    int t = blockIdx.x * blockDim.x + threadIdx.x;
    if (t < HSIZE) { g_keys[t] = 0u; g_vals[t] = 0; }
    if (t == 0) g_paircnt = 0;
}

// ---------------------------------------------------------------------------
// Replicates: xyz = a*(hi-lo)+lo ; idx = (int)((xyz-lo)/0.1f)  (all fp32, no fma)
__global__ void k_insert(const float* __restrict__ anchor) {
    int i = blockIdx.x * blockDim.x + threadIdx.x;
    if (i >= NPTS) return;

    float ax = anchor[3 * i + 0];
    float ay = anchor[3 * i + 1];
    float az = anchor[3 * i + 2];

    const float lox = -20.0f, loy = -20.0f, loz = -2.3f;
    const float spanx = __fsub_rn(20.0f, -20.0f);
    const float spany = __fsub_rn(20.0f, -20.0f);
    const float spanz = __fsub_rn(0.9f, -2.3f);
    const float step  = 0.1f;

    float xx = __fadd_rn(__fmul_rn(ax, spanx), lox);
    float yy = __fadd_rn(__fmul_rn(ay, spany), loy);
    float zz = __fadd_rn(__fmul_rn(az, spanz), loz);

    int ix = (int)__fdiv_rn(__fsub_rn(xx, lox), step);
    int iy = (int)__fdiv_rn(__fsub_rn(yy, loy), step);
    int iz = (int)__fdiv_rn(__fsub_rn(zz, loz), step);

    g_pidx[i] = (ix << 14) | (iy << 5) | iz;   // ix:9b iy:9b iz:5b

    if (ix >= 0 && ix < DX && iy >= 0 && iy < DY && iz >= 0 && iz < DZ) {
        int b = i / GPT;
        unsigned int key = 1u + (unsigned int)((((b * DX + ix) * DY + iy) * DZ) + iz);
        unsigned int h = hash_key(key);
        while (true) {
            unsigned int old = atomicCAS(&g_keys[h], 0u, key);
            if (old == 0u || old == key) {
                atomicMax(&g_vals[h], i + 1);   // last-update-wins == max index
                break;
            }
            h = (h + 1) & HMASK;
        }
    }
}

// ---------------------------------------------------------------------------
__device__ __forceinline__ int hash_lookup(int b, int nx, int ny, int nz) {
    unsigned int key = 1u + (unsigned int)((((b * DX + nx) * DY + ny) * DZ) + nz);
    unsigned int h = hash_key(key);
    while (true) {
        unsigned int kk = g_keys[h];
        if (kk == key) return g_vals[h] - 1;
        if (kk == 0u) return -1;
        h = (h + 1) & HMASK;
    }
}

__global__ void k_pairs() {
    int tid = blockIdx.x * blockDim.x + threadIdx.x;
    if (tid >= NPTS * KOFF) return;
    int i = tid / KOFF;
    int k = tid - i * KOFF;

    int p  = g_pidx[i];
    int ix = p >> 14, iy = (p >> 5) & 0x1FF, iz = p & 0x1F;
    int ox = k / 25 - 2;
    int oy = (k / 5) % 5 - 2;
    int oz = k % 5 - 2;
    int nx = ix + ox, ny = iy + oy, nz = iz + oz;

    int j = -1;
    if (nx >= 0 && nx < DX && ny >= 0 && ny < DY && nz >= 0 && nz < DZ) {
        j = hash_lookup(i / GPT, nx, ny, nz);
    }

    if (k == KC) {
        g_jc[i] = j;
    } else if (j >= 0) {
        int pos = atomicAdd(&g_paircnt, 1);
        if (pos < MAXP) {
            g_pairs[3 * pos + 0] = i;
            g_pairs[3 * pos + 1] = k;
            g_pairs[3 * pos + 2] = j;
        }
    }
}

// ---------------------------------------------------------------------------
// out[rowbase .. rowbase+63][0..127] = feats[jc[row]] @ w[62]
#define BM 64
__global__ void __launch_bounds__(256) k_gemm(const float* __restrict__ feats,
                                              const float* __restrict__ w,
                                              float* __restrict__ out) {
    __shared__ float As[BM][32];
    __shared__ float Bs[32][128];
    __shared__ int   jrow[BM];

    int tid = threadIdx.x;                 // 256 threads
    int tx = tid & 31;                     // col group: cols tx*4 .. tx*4+3
    int ty = tid >> 5;                     // row group: rows ty*8 .. ty*8+7
    int rowbase = blockIdx.x * BM;
    const float* w62 = w + KC * CIN * COUT;

    if (tid < BM) jrow[tid] = g_jc[rowbase + tid];
    __syncthreads();

    float acc[8][4];
#pragma unroll
    for (int r = 0; r < 8; r++)
#pragma unroll
        for (int c = 0; c < 4; c++) acc[r][c] = 0.0f;

    for (int c0 = 0; c0 < CIN; c0 += 32) {
        // load A chunk: 64 rows x 32 cols = 512 float4
#pragma unroll
        for (int q = tid; q < 512; q += 256) {
            int r = q >> 3, c4 = q & 7;
            int src = jrow[r];
            float4 v = make_float4(0.f, 0.f, 0.f, 0.f);
            if (src >= 0) v = ((const float4*)(feats + src * CIN + c0))[c4];
            ((float4*)&As[r][0])[c4] = v;
        }
        // load B chunk: 32 x 128 = 1024 float4
#pragma unroll
        for (int q = tid; q < 1024; q += 256) {
            int cc = q >> 5, c4 = q & 31;
            ((float4*)&Bs[cc][0])[c4] = ((const float4*)(w62 + (c0 + cc) * COUT))[c4];
        }
        __syncthreads();

#pragma unroll
        for (int cc = 0; cc < 32; cc++) {
            float4 b = ((float4*)&Bs[cc][0])[tx];
#pragma unroll
            for (int r = 0; r < 8; r++) {
                float a = As[ty * 8 + r][cc];
                acc[r][0] += a * b.x;
                acc[r][1] += a * b.y;
                acc[r][2] += a * b.z;
                acc[r][3] += a * b.w;
            }
        }
        __syncthreads();
    }

#pragma unroll
    for (int r = 0; r < 8; r++) {
        int row = rowbase + ty * 8 + r;
        ((float4*)(out + row * COUT))[tx] =
            make_float4(acc[r][0], acc[r][1], acc[r][2], acc[r][3]);
    }
}

// ---------------------------------------------------------------------------
// apply rare non-center neighbor contributions: out[i] += feats[j] @ w[k]
__global__ void k_apply(const float* __restrict__ feats,
                        const float* __restrict__ w,
                        float* __restrict__ out) {
    int cnt = g_paircnt;
    if (cnt > MAXP) cnt = MAXP;
    int t = threadIdx.x;   // 128
    for (int p = blockIdx.x; p < cnt; p += gridDim.x) {
        int i = g_pairs[3 * p + 0];
        int k = g_pairs[3 * p + 1];
        int j = g_pairs[3 * p + 2];
        const float* f  = feats + j * CIN;
        const float* wk = w + k * CIN * COUT;
        float acc = 0.0f;
#pragma unroll 8
        for (int c = 0; c < CIN; c++)
            acc += __ldg(f + c) * wk[c * COUT + t];
        atomicAdd(out + i * COUT + t, acc);
    }
}

// ---------------------------------------------------------------------------
extern "C" void kernel_launch(void* const* d_in, const int* in_sizes, int n_in,
                              void* d_out, int out_size) {
    const float* feats  = (const float*)d_in[0];
    const float* anchor = (const float*)d_in[1];
    const float* w      = (const float*)d_in[2];
    float* out = (float*)d_out;

    k_clear<<<HSIZE / 256, 256>>>();
    k_insert<<<(NPTS + 255) / 256, 256>>>(anchor);
    k_pairs<<<(NPTS * KOFF + 255) / 256, 256>>>();
    k_gemm<<<NPTS / BM, 256>>>(feats, w, out);
    k_apply<<<128, 128>>>(feats, w, out);
}